// round 1
// baseline (speedup 1.0000x reference)
#include <cuda_runtime.h>
#include <cuda_bf16.h>
#include <math.h>

#define NN 50000
#define NE 800000

// ---------------- scratch (device globals; no allocs allowed) ----------------
__device__ float g_x[NN * 128];      // gated x
__device__ float g_h[NN * 256];      // current layer h = x @ W
__device__ float g_z1[NN * 256];
__device__ float g_z2[NN * 256];
__device__ float g_res[NN * 256];    // residual buffer (xr1, then z1@r2)
__device__ float g_zself[NN * 64];
__device__ float g_t64[NN * 64];     // ffn hidden / h3
__device__ float g_asrc[NN * 4];
__device__ float g_adst[NN * 4];
__device__ float g_loop[NN];
__device__ float g_easum[NN];
__device__ int   g_deg[NN];
__device__ int   g_rowstart[NN];
__device__ int   g_cursor[NN];
__device__ int   g_csr[NE];
__device__ float g_ch[4];

// ---------------- GEMM: C[M,N] = A[M,K] @ B[K,N] (+bias, epilogue) ----------
// BM=BN=64, BK=16, 16x16 threads, 4x4 per thread. K%16==0, N%64==0 guaranteed.
#define EP_NONE 0
#define EP_GATE 1   // out = A[row,col] * sigmoid(acc + bias)   (requires K==N)
#define EP_RELU 2

__device__ __forceinline__ float sigf(float x) { return 1.f / (1.f + __expf(-x)); }

template <int EP>
__global__ void gemm_kernel(const float* __restrict__ A, const float* __restrict__ B,
                            const float* __restrict__ bias, float* __restrict__ C,
                            int M, int K, int N) {
    __shared__ float As[16][64];
    __shared__ float Bs[16][64];
    const int bm = blockIdx.y * 64, bn = blockIdx.x * 64;
    const int tx = threadIdx.x, ty = threadIdx.y;
    const int tid = ty * 16 + tx;
    float acc[4][4] = {};
    for (int k0 = 0; k0 < K; k0 += 16) {
#pragma unroll
        for (int i = 0; i < 4; i++) {
            int idx = tid + i * 256;
            int m = idx >> 4, kk = idx & 15;
            int row = bm + m;
            As[kk][m] = (row < M) ? A[(size_t)row * K + k0 + kk] : 0.f;
        }
#pragma unroll
        for (int i = 0; i < 4; i++) {
            int idx = tid + i * 256;
            int kk = idx >> 6, nn = idx & 63;
            Bs[kk][nn] = B[(size_t)(k0 + kk) * N + bn + nn];
        }
        __syncthreads();
#pragma unroll
        for (int kk = 0; kk < 16; kk++) {
            float ra[4], rb[4];
#pragma unroll
            for (int i = 0; i < 4; i++) ra[i] = As[kk][ty * 4 + i];
#pragma unroll
            for (int j = 0; j < 4; j++) rb[j] = Bs[kk][tx * 4 + j];
#pragma unroll
            for (int i = 0; i < 4; i++)
#pragma unroll
                for (int j = 0; j < 4; j++) acc[i][j] += ra[i] * rb[j];
        }
        __syncthreads();
    }
#pragma unroll
    for (int i = 0; i < 4; i++) {
        int row = bm + ty * 4 + i;
        if (row >= M) continue;
#pragma unroll
        for (int j = 0; j < 4; j++) {
            int col = bn + tx * 4 + j;
            float v = acc[i][j] + (bias ? bias[col] : 0.f);
            if (EP == EP_GATE) v = A[(size_t)row * K + col] * sigf(v);
            else if (EP == EP_RELU) v = fmaxf(v, 0.f);
            C[(size_t)row * N + col] = v;
        }
    }
}

static void launch_gemm(int ep, const float* A, const float* B, const float* bias,
                        float* C, int M, int K, int N) {
    dim3 grid((N + 63) / 64, (M + 63) / 64), blk(16, 16);
    if (ep == EP_NONE) gemm_kernel<EP_NONE><<<grid, blk>>>(A, B, bias, C, M, K, N);
    else if (ep == EP_GATE) gemm_kernel<EP_GATE><<<grid, blk>>>(A, B, bias, C, M, K, N);
    else gemm_kernel<EP_RELU><<<grid, blk>>>(A, B, bias, C, M, K, N);
}

// ---------------- CSR build ----------------
__global__ void zero_kernel() {
    int i = blockIdx.x * blockDim.x + threadIdx.x;
    if (i < NN) { g_deg[i] = 0; g_cursor[i] = 0; g_easum[i] = 0.f; }
}
__global__ void deg_kernel(const int* __restrict__ dst, const float* __restrict__ ea) {
    int e = blockIdx.x * blockDim.x + threadIdx.x;
    if (e < NE) {
        int d = dst[e];
        atomicAdd(&g_deg[d], 1);
        atomicAdd(&g_easum[d], ea[e]);
    }
}
__global__ void loop_kernel() {
    int n = blockIdx.x * blockDim.x + threadIdx.x;
    if (n < NN) g_loop[n] = g_easum[n] / fmaxf((float)g_deg[n], 1.f);
}
// exclusive scan of g_deg into g_rowstart; single block, 1024 threads
__global__ void scan_kernel() {
    __shared__ int s[1024];
    int tid = threadIdx.x;
    int running = 0;
    for (int base = 0; base < NN; base += 1024) {
        int val = (base + tid < NN) ? g_deg[base + tid] : 0;
        s[tid] = val;
        __syncthreads();
        for (int off = 1; off < 1024; off <<= 1) {
            int t = (tid >= off) ? s[tid - off] : 0;
            __syncthreads();
            s[tid] += t;
            __syncthreads();
        }
        if (base + tid < NN) g_rowstart[base + tid] = running + s[tid] - val;
        int total = s[1023];
        __syncthreads();
        running += total;
    }
}
__global__ void csr_kernel(const int* __restrict__ dst) {
    int e = blockIdx.x * blockDim.x + threadIdx.x;
    if (e < NE) {
        int d = dst[e];
        int pos = atomicAdd(&g_cursor[d], 1);
        g_csr[g_rowstart[d] + pos] = e;
    }
}

// ---------------- attention coefficients ----------------
// a_src[n,h] = sum_c h[n,h,c]*a_s[h,c]; same for a_dst. C=64 fixed. warp per (n,h).
template <int H>
__global__ void attn_kernel(const float* __restrict__ hbuf, const float* __restrict__ a_s,
                            const float* __restrict__ a_d) {
    int w = (blockIdx.x * blockDim.x + threadIdx.x) >> 5;
    int lane = threadIdx.x & 31;
    if (w >= NN * H) return;
    int n = w / H, hh = w % H;
    const float* hr = hbuf + (size_t)n * H * 64 + hh * 64;
    float as0 = a_s[hh * 64 + lane], as1 = a_s[hh * 64 + lane + 32];
    float ad0 = a_d[hh * 64 + lane], ad1 = a_d[hh * 64 + lane + 32];
    float h0 = hr[lane], h1 = hr[lane + 32];
    float vs = h0 * as0 + h1 * as1;
    float vd = h0 * ad0 + h1 * ad1;
#pragma unroll
    for (int off = 16; off > 0; off >>= 1) {
        vs += __shfl_down_sync(0xffffffffu, vs, off);
        vd += __shfl_down_sync(0xffffffffu, vd, off);
    }
    if (lane == 0) { g_asrc[w] = vs; g_adst[w] = vd; }
}

__global__ void ch_kernel(const float* __restrict__ We, const float* __restrict__ ae, int H, int C) {
    int h = threadIdx.x;
    if (h < H) {
        float s = 0.f;
        for (int c = 0; c < C; c++) s += We[h * C + c] * ae[h * C + c];
        g_ch[h] = s;
    }
}

// ---------------- per-node softmax aggregation ----------------
// block per node, blockDim = H*C. out[n,c] = lrelu(sum_e alpha*h[s,c] + bias, .01) + resid
template <int H, int C>
__global__ void agg_kernel(const float* __restrict__ hbuf, const int* __restrict__ src,
                           const float* __restrict__ ea, const float* __restrict__ bias,
                           const float* __restrict__ resid, float* __restrict__ out) {
    constexpr int OUT = H * C;
    constexpr int CH = 64;
    __shared__ float s_m[H], s_z[H], s_adst[H], s_chh[H];
    __shared__ float s_red[OUT];
    __shared__ float s_alpha[CH * H];
    __shared__ int s_sid[CH];

    const int n = blockIdx.x;
    const int tid = threadIdx.x;
    const int deg = g_deg[n];
    const int rs = g_rowstart[n];
    const int T = deg + 1;  // + self loop
    const float loopv = g_loop[n];

    if (tid < H) { s_adst[tid] = g_adst[n * H + tid]; s_chh[tid] = g_ch[tid]; }
    __syncthreads();

    // pass 1: max per head
    float lm[H];
#pragma unroll
    for (int h = 0; h < H; h++) lm[h] = -1e30f;
    for (int i = tid; i < T; i += OUT) {
        int sN; float eav;
        if (i < deg) { int e = g_csr[rs + i]; sN = src[e]; eav = ea[e]; }
        else { sN = n; eav = loopv; }
#pragma unroll
        for (int h = 0; h < H; h++) {
            float v = g_asrc[sN * H + h] + s_adst[h] + s_chh[h] * eav;
            v = (v >= 0.f) ? v : 0.2f * v;
            lm[h] = fmaxf(lm[h], v);
        }
    }
#pragma unroll
    for (int h = 0; h < H; h++) {
        s_red[tid] = lm[h];
        __syncthreads();
        for (int off = OUT / 2; off > 0; off >>= 1) {
            if (tid < off) s_red[tid] = fmaxf(s_red[tid], s_red[tid + off]);
            __syncthreads();
        }
        if (tid == 0) s_m[h] = s_red[0];
        __syncthreads();
    }

    // pass 2: Z per head
    float lz[H];
#pragma unroll
    for (int h = 0; h < H; h++) lz[h] = 0.f;
    for (int i = tid; i < T; i += OUT) {
        int sN; float eav;
        if (i < deg) { int e = g_csr[rs + i]; sN = src[e]; eav = ea[e]; }
        else { sN = n; eav = loopv; }
#pragma unroll
        for (int h = 0; h < H; h++) {
            float v = g_asrc[sN * H + h] + s_adst[h] + s_chh[h] * eav;
            v = (v >= 0.f) ? v : 0.2f * v;
            lz[h] += expf(v - s_m[h]);
        }
    }
#pragma unroll
    for (int h = 0; h < H; h++) {
        s_red[tid] = lz[h];
        __syncthreads();
        for (int off = OUT / 2; off > 0; off >>= 1) {
            if (tid < off) s_red[tid] += s_red[tid + off];
            __syncthreads();
        }
        if (tid == 0) s_z[h] = s_red[0];
        __syncthreads();
    }

    // pass 3: chunked alpha + gather-accumulate
    const int hh = tid / C;
    float acc = 0.f;
    for (int base = 0; base < T; base += CH) {
        int i = base + tid;
        if (tid < CH && i < T) {
            int sN; float eav;
            if (i < deg) { int e = g_csr[rs + i]; sN = src[e]; eav = ea[e]; }
            else { sN = n; eav = loopv; }
#pragma unroll
            for (int h = 0; h < H; h++) {
                float v = g_asrc[sN * H + h] + s_adst[h] + s_chh[h] * eav;
                v = (v >= 0.f) ? v : 0.2f * v;
                s_alpha[tid * H + h] = expf(v - s_m[h]) / s_z[h];
            }
            s_sid[tid] = sN;
        }
        __syncthreads();
        int lim = min(CH, T - base);
        for (int j = 0; j < lim; j++)
            acc += s_alpha[j * H + hh] * hbuf[(size_t)s_sid[j] * OUT + tid];
        __syncthreads();
    }
    float v = acc + bias[tid];
    v = (v >= 0.f) ? v : 0.01f * v;
    out[(size_t)n * OUT + tid] = v + resid[(size_t)n * OUT + tid];
}

// ---------------- driver ----------------
extern "C" void kernel_launch(void* const* d_in, const int* in_sizes, int n_in,
                              void* d_out, int out_size) {
    const float* x     = (const float*)d_in[0];
    const int*   eidx  = (const int*)d_in[1];
    const float* ea    = (const float*)d_in[2];
    const float* fa_w  = (const float*)d_in[3];
    const float* fa_b  = (const float*)d_in[4];
    const float* W1    = (const float*)d_in[5];
    const float* We1   = (const float*)d_in[6];
    const float* as1   = (const float*)d_in[7];
    const float* ad1   = (const float*)d_in[8];
    const float* ae1   = (const float*)d_in[9];
    const float* b1    = (const float*)d_in[10];
    const float* W2    = (const float*)d_in[11];
    const float* We2   = (const float*)d_in[12];
    const float* as2   = (const float*)d_in[13];
    const float* ad2   = (const float*)d_in[14];
    const float* ae2   = (const float*)d_in[15];
    const float* b2    = (const float*)d_in[16];
    const float* W3    = (const float*)d_in[17];
    const float* We3   = (const float*)d_in[18];
    const float* as3   = (const float*)d_in[19];
    const float* ad3   = (const float*)d_in[20];
    const float* ae3   = (const float*)d_in[21];
    const float* b3    = (const float*)d_in[22];
    const float* r1_w  = (const float*)d_in[23];
    const float* r1_b  = (const float*)d_in[24];
    const float* r2_w  = (const float*)d_in[25];
    const float* r2_b  = (const float*)d_in[26];
    const float* ffn_w1 = (const float*)d_in[27];
    const float* ffn_b1 = (const float*)d_in[28];
    const float* ffn_w2 = (const float*)d_in[29];
    const float* ffn_b2 = (const float*)d_in[30];
    float* out = (float*)d_out;

    const int* src = eidx;
    const int* dst = eidx + NE;

    float *gx, *gh, *gz1, *gz2, *gres, *gzself, *gt64;
    cudaGetSymbolAddress((void**)&gx, g_x);
    cudaGetSymbolAddress((void**)&gh, g_h);
    cudaGetSymbolAddress((void**)&gz1, g_z1);
    cudaGetSymbolAddress((void**)&gz2, g_z2);
    cudaGetSymbolAddress((void**)&gres, g_res);
    cudaGetSymbolAddress((void**)&gzself, g_zself);
    cudaGetSymbolAddress((void**)&gt64, g_t64);

    const int TB = 256;
    const int nbN = (NN + TB - 1) / TB;
    const int nbE = (NE + TB - 1) / TB;

    // CSR build (feature-independent)
    zero_kernel<<<nbN, TB>>>();
    deg_kernel<<<nbE, TB>>>(dst, ea);
    loop_kernel<<<nbN, TB>>>();
    scan_kernel<<<1, 1024>>>();
    csr_kernel<<<nbE, TB>>>(dst);

    // feature gate: g_x = x * sigmoid(x @ fa_w + fa_b)
    launch_gemm(EP_GATE, x, fa_w, fa_b, gx, NN, 128, 128);

    // z_self = relu(g_x @ ffn_w1 + b) @ ffn_w2 + b
    launch_gemm(EP_RELU, gx, ffn_w1, ffn_b1, gt64, NN, 128, 64);
    launch_gemm(EP_NONE, gt64, ffn_w2, ffn_b2, gzself, NN, 64, 64);

    // --- layer 1 ---
    launch_gemm(EP_NONE, gx, r1_w, r1_b, gres, NN, 128, 256);
    launch_gemm(EP_NONE, gx, W1, nullptr, gh, NN, 128, 256);
    attn_kernel<4><<<(NN * 4 * 32 + TB - 1) / TB, TB>>>(gh, as1, ad1);
    ch_kernel<<<1, 4>>>(We1, ae1, 4, 64);
    agg_kernel<4, 64><<<NN, 256>>>(gh, src, ea, b1, gres, gz1);

    // --- layer 2 ---
    launch_gemm(EP_NONE, gz1, r2_w, r2_b, gres, NN, 256, 256);
    launch_gemm(EP_NONE, gz1, W2, nullptr, gh, NN, 256, 256);
    attn_kernel<4><<<(NN * 4 * 32 + TB - 1) / TB, TB>>>(gh, as2, ad2);
    ch_kernel<<<1, 4>>>(We2, ae2, 4, 64);
    agg_kernel<4, 64><<<NN, 256>>>(gh, src, ea, b2, gres, gz2);

    // --- layer 3 (H=1, C=64) ---
    launch_gemm(EP_NONE, gz2, W3, nullptr, gt64, NN, 256, 64);
    attn_kernel<1><<<(NN * 32 + TB - 1) / TB, TB>>>(gt64, as3, ad3);
    ch_kernel<<<1, 1>>>(We3, ae3, 1, 64);
    agg_kernel<1, 64><<<NN, 64>>>(gt64, src, ea, b3, gzself, out);
}

// round 2
// speedup vs baseline: 1.1527x; 1.1527x over previous
#include <cuda_runtime.h>
#include <cuda_bf16.h>
#include <math.h>
#include <stdint.h>

#define NN 50000
#define NE 800000

// ---------------- scratch (device globals; no allocs allowed) ----------------
__device__ float g_x[NN * 128];      // gated x
__device__ float g_h[NN * 256];      // current layer h = x @ W
__device__ float g_z1[NN * 256];
__device__ float g_z2[NN * 256];
__device__ float g_res[NN * 256];    // residual buffer (xr1, then z1@r2)
__device__ float g_zself[NN * 64];
__device__ float g_t64[NN * 64];     // ffn hidden / h3
__device__ float g_asrc[NN * 4];
__device__ float g_adst[NN * 4];
__device__ float g_loop[NN];
__device__ float g_easum[NN];
__device__ int   g_deg[NN];
__device__ int   g_rowstart[NN];
__device__ int   g_cursor[NN];
__device__ int   g_csr[NE];
__device__ float g_ch[4];
__device__ int   g_total;

// ---------------- TF32 tensor-core GEMM (3xTF32 error-compensated) ----------
// C[M,N] = A[M,K] @ B[K,N] (+bias, epilogue). BM=128, BN=64, BK=16.
// 256 threads = 8 warps (4x2), warp tile 32x32 = 2 (m16) x 4 (n8) mma tiles.
#define EP_NONE 0
#define EP_GATE 1   // out = A[row,col] * sigmoid(acc + bias)   (requires K==N)
#define EP_RELU 2

__device__ __forceinline__ float sigf(float x) { return 1.f / (1.f + __expf(-x)); }

__device__ __forceinline__ void tf32_split(float x, float& hi, float& lo) {
    uint32_t uh;
    asm("cvt.rna.tf32.f32 %0, %1;" : "=r"(uh) : "f"(x));
    hi = __uint_as_float(uh);
    float r = x - hi;
    uint32_t ul;
    asm("cvt.rna.tf32.f32 %0, %1;" : "=r"(ul) : "f"(r));
    lo = __uint_as_float(ul);
}

__device__ __forceinline__ void mma_tf32(float* c, const uint32_t* a, const uint32_t* b) {
    asm volatile(
        "mma.sync.aligned.m16n8k8.row.col.f32.tf32.tf32.f32 "
        "{%0,%1,%2,%3}, {%4,%5,%6,%7}, {%8,%9}, {%0,%1,%2,%3};\n"
        : "+f"(c[0]), "+f"(c[1]), "+f"(c[2]), "+f"(c[3])
        : "r"(a[0]), "r"(a[1]), "r"(a[2]), "r"(a[3]), "r"(b[0]), "r"(b[1]));
}

template <int EP>
__global__ __launch_bounds__(256) void gemm_tf32(
    const float* __restrict__ A, const float* __restrict__ B,
    const float* __restrict__ bias, float* __restrict__ C,
    int M, int K, int N) {
    __shared__ float Ah[128][20], Al[128][20];
    __shared__ float Bh[64][20],  Bl[64][20];
    const int bm = blockIdx.y * 128, bn = blockIdx.x * 64;
    const int tid = threadIdx.x, lane = tid & 31, wid = tid >> 5;
    const int wm = wid >> 1, wn = wid & 1;   // 4 x 2 warp grid
    const int lg = lane >> 2;                // group id 0..7
    const int lt = lane & 3;                 // thread-in-group 0..3

    float acc[2][4][4];
#pragma unroll
    for (int mt = 0; mt < 2; mt++)
#pragma unroll
        for (int nt = 0; nt < 4; nt++)
#pragma unroll
            for (int j = 0; j < 4; j++) acc[mt][nt][j] = 0.f;

    for (int k0 = 0; k0 < K; k0 += 16) {
        // load A tile: 128 rows x 16 cols = 512 float4, 2 per thread
#pragma unroll
        for (int t = 0; t < 2; t++) {
            int i = tid + t * 256;
            int r = i >> 2, s = (i & 3) * 4;
            float4 v = make_float4(0.f, 0.f, 0.f, 0.f);
            if (bm + r < M) v = *(const float4*)&A[(size_t)(bm + r) * K + k0 + s];
            float h0, l0;
            tf32_split(v.x, h0, l0); Ah[r][s + 0] = h0; Al[r][s + 0] = l0;
            tf32_split(v.y, h0, l0); Ah[r][s + 1] = h0; Al[r][s + 1] = l0;
            tf32_split(v.z, h0, l0); Ah[r][s + 2] = h0; Al[r][s + 2] = l0;
            tf32_split(v.w, h0, l0); Ah[r][s + 3] = h0; Al[r][s + 3] = l0;
        }
        // load B tile: 16 rows x 64 cols = 256 float4, 1 per thread; store [n][k]
        {
            int kk = tid >> 4, n4 = (tid & 15) * 4;
            float4 v = *(const float4*)&B[(size_t)(k0 + kk) * N + bn + n4];
            float h0, l0;
            tf32_split(v.x, h0, l0); Bh[n4 + 0][kk] = h0; Bl[n4 + 0][kk] = l0;
            tf32_split(v.y, h0, l0); Bh[n4 + 1][kk] = h0; Bl[n4 + 1][kk] = l0;
            tf32_split(v.z, h0, l0); Bh[n4 + 2][kk] = h0; Bl[n4 + 2][kk] = l0;
            tf32_split(v.w, h0, l0); Bh[n4 + 3][kk] = h0; Bl[n4 + 3][kk] = l0;
        }
        __syncthreads();
#pragma unroll
        for (int ks = 0; ks < 16; ks += 8) {
            const int kc = ks + lt;
            uint32_t ah[2][4], al[2][4], bh[4][2], bl[4][2];
#pragma unroll
            for (int mt = 0; mt < 2; mt++) {
                int r = wm * 32 + mt * 16 + lg;
                ah[mt][0] = __float_as_uint(Ah[r][kc]);
                ah[mt][1] = __float_as_uint(Ah[r + 8][kc]);
                ah[mt][2] = __float_as_uint(Ah[r][kc + 4]);
                ah[mt][3] = __float_as_uint(Ah[r + 8][kc + 4]);
                al[mt][0] = __float_as_uint(Al[r][kc]);
                al[mt][1] = __float_as_uint(Al[r + 8][kc]);
                al[mt][2] = __float_as_uint(Al[r][kc + 4]);
                al[mt][3] = __float_as_uint(Al[r + 8][kc + 4]);
            }
#pragma unroll
            for (int nt = 0; nt < 4; nt++) {
                int c = wn * 32 + nt * 8 + lg;
                bh[nt][0] = __float_as_uint(Bh[c][kc]);
                bh[nt][1] = __float_as_uint(Bh[c][kc + 4]);
                bl[nt][0] = __float_as_uint(Bl[c][kc]);
                bl[nt][1] = __float_as_uint(Bl[c][kc + 4]);
            }
#pragma unroll
            for (int mt = 0; mt < 2; mt++)
#pragma unroll
                for (int nt = 0; nt < 4; nt++) {
                    mma_tf32(acc[mt][nt], ah[mt], bh[nt]);
                    mma_tf32(acc[mt][nt], al[mt], bh[nt]);
                    mma_tf32(acc[mt][nt], ah[mt], bl[nt]);
                }
        }
        __syncthreads();
    }
    // epilogue
#pragma unroll
    for (int mt = 0; mt < 2; mt++) {
        int r0 = bm + wm * 32 + mt * 16 + lg;
#pragma unroll
        for (int nt = 0; nt < 4; nt++) {
            int c0 = bn + wn * 32 + nt * 8 + lt * 2;
#pragma unroll
            for (int j = 0; j < 4; j++) {
                int row = r0 + (j >> 1) * 8;
                int col = c0 + (j & 1);
                if (row >= M) continue;
                float v = acc[mt][nt][j] + (bias ? bias[col] : 0.f);
                if (EP == EP_GATE) v = A[(size_t)row * K + col] * sigf(v);
                else if (EP == EP_RELU) v = fmaxf(v, 0.f);
                C[(size_t)row * N + col] = v;
            }
        }
    }
}

static void launch_gemm(int ep, const float* A, const float* B, const float* bias,
                        float* C, int M, int K, int N) {
    dim3 grid(N / 64, (M + 127) / 128), blk(256);
    if (ep == EP_NONE) gemm_tf32<EP_NONE><<<grid, blk>>>(A, B, bias, C, M, K, N);
    else if (ep == EP_GATE) gemm_tf32<EP_GATE><<<grid, blk>>>(A, B, bias, C, M, K, N);
    else gemm_tf32<EP_RELU><<<grid, blk>>>(A, B, bias, C, M, K, N);
}

// ---------------- CSR build ----------------
__global__ void zero_kernel() {
    int i = blockIdx.x * blockDim.x + threadIdx.x;
    if (i < NN) { g_deg[i] = 0; g_cursor[i] = 0; g_easum[i] = 0.f; }
    if (i == 0) g_total = 0;
}
__global__ void deg_kernel(const int* __restrict__ dst, const float* __restrict__ ea) {
    int e = blockIdx.x * blockDim.x + threadIdx.x;
    if (e < NE) {
        int d = dst[e];
        atomicAdd(&g_deg[d], 1);
        atomicAdd(&g_easum[d], ea[e]);
    }
}
__global__ void loop_kernel() {
    int n = blockIdx.x * blockDim.x + threadIdx.x;
    if (n < NN) g_loop[n] = g_easum[n] / fmaxf((float)g_deg[n], 1.f);
}
// rowstart allocation: per-block scan + one atomicAdd per block (order-free)
__global__ void alloc_kernel() {
    __shared__ int s[1024];
    __shared__ int base;
    int tid = threadIdx.x;
    int i = blockIdx.x * 1024 + tid;
    int v = (i < NN) ? g_deg[i] : 0;
    s[tid] = v;
    __syncthreads();
    for (int off = 1; off < 1024; off <<= 1) {
        int t = (tid >= off) ? s[tid - off] : 0;
        __syncthreads();
        s[tid] += t;
        __syncthreads();
    }
    int incl = s[tid];
    if (tid == 1023) base = atomicAdd(&g_total, s[1023]);
    __syncthreads();
    if (i < NN) g_rowstart[i] = base + incl - v;
}
__global__ void csr_kernel(const int* __restrict__ dst) {
    int e = blockIdx.x * blockDim.x + threadIdx.x;
    if (e < NE) {
        int d = dst[e];
        int pos = atomicAdd(&g_cursor[d], 1);
        g_csr[g_rowstart[d] + pos] = e;
    }
}

// ---------------- attention coefficients ----------------
template <int H>
__global__ void attn_kernel(const float* __restrict__ hbuf, const float* __restrict__ a_s,
                            const float* __restrict__ a_d) {
    int w = (blockIdx.x * blockDim.x + threadIdx.x) >> 5;
    int lane = threadIdx.x & 31;
    if (w >= NN * H) return;
    int n = w / H, hh = w % H;
    const float* hr = hbuf + (size_t)n * H * 64 + hh * 64;
    float as0 = a_s[hh * 64 + lane], as1 = a_s[hh * 64 + lane + 32];
    float ad0 = a_d[hh * 64 + lane], ad1 = a_d[hh * 64 + lane + 32];
    float h0 = hr[lane], h1 = hr[lane + 32];
    float vs = h0 * as0 + h1 * as1;
    float vd = h0 * ad0 + h1 * ad1;
#pragma unroll
    for (int off = 16; off > 0; off >>= 1) {
        vs += __shfl_down_sync(0xffffffffu, vs, off);
        vd += __shfl_down_sync(0xffffffffu, vd, off);
    }
    if (lane == 0) { g_asrc[w] = vs; g_adst[w] = vd; }
}

__global__ void ch_kernel(const float* __restrict__ We, const float* __restrict__ ae, int H, int C) {
    int h = threadIdx.x;
    if (h < H) {
        float s = 0.f;
        for (int c = 0; c < C; c++) s += We[h * C + c] * ae[h * C + c];
        g_ch[h] = s;
    }
}

// ---------------- per-node softmax aggregation ----------------
template <int H, int C>
__global__ void agg_kernel(const float* __restrict__ hbuf, const int* __restrict__ src,
                           const float* __restrict__ ea, const float* __restrict__ bias,
                           const float* __restrict__ resid, float* __restrict__ out) {
    constexpr int OUT = H * C;
    constexpr int CH = 64;
    __shared__ float s_m[H], s_z[H], s_adst[H], s_chh[H];
    __shared__ float s_red[OUT];
    __shared__ float s_alpha[CH * H];
    __shared__ int s_sid[CH];

    const int n = blockIdx.x;
    const int tid = threadIdx.x;
    const int deg = g_deg[n];
    const int rs = g_rowstart[n];
    const int T = deg + 1;  // + self loop
    const float loopv = g_loop[n];

    if (tid < H) { s_adst[tid] = g_adst[n * H + tid]; s_chh[tid] = g_ch[tid]; }
    __syncthreads();

    // pass 1: max per head
    float lm[H];
#pragma unroll
    for (int h = 0; h < H; h++) lm[h] = -1e30f;
    for (int i = tid; i < T; i += OUT) {
        int sN; float eav;
        if (i < deg) { int e = g_csr[rs + i]; sN = src[e]; eav = ea[e]; }
        else { sN = n; eav = loopv; }
#pragma unroll
        for (int h = 0; h < H; h++) {
            float v = g_asrc[sN * H + h] + s_adst[h] + s_chh[h] * eav;
            v = (v >= 0.f) ? v : 0.2f * v;
            lm[h] = fmaxf(lm[h], v);
        }
    }
#pragma unroll
    for (int h = 0; h < H; h++) {
        s_red[tid] = lm[h];
        __syncthreads();
        for (int off = OUT / 2; off > 0; off >>= 1) {
            if (tid < off) s_red[tid] = fmaxf(s_red[tid], s_red[tid + off]);
            __syncthreads();
        }
        if (tid == 0) s_m[h] = s_red[0];
        __syncthreads();
    }

    // pass 2: Z per head
    float lz[H];
#pragma unroll
    for (int h = 0; h < H; h++) lz[h] = 0.f;
    for (int i = tid; i < T; i += OUT) {
        int sN; float eav;
        if (i < deg) { int e = g_csr[rs + i]; sN = src[e]; eav = ea[e]; }
        else { sN = n; eav = loopv; }
#pragma unroll
        for (int h = 0; h < H; h++) {
            float v = g_asrc[sN * H + h] + s_adst[h] + s_chh[h] * eav;
            v = (v >= 0.f) ? v : 0.2f * v;
            lz[h] += expf(v - s_m[h]);
        }
    }
#pragma unroll
    for (int h = 0; h < H; h++) {
        s_red[tid] = lz[h];
        __syncthreads();
        for (int off = OUT / 2; off > 0; off >>= 1) {
            if (tid < off) s_red[tid] += s_red[tid + off];
            __syncthreads();
        }
        if (tid == 0) s_z[h] = s_red[0];
        __syncthreads();
    }

    // pass 3: chunked alpha + gather-accumulate
    const int hh = tid / C;
    float acc = 0.f;
    for (int base = 0; base < T; base += CH) {
        int i = base + tid;
        if (tid < CH && i < T) {
            int sN; float eav;
            if (i < deg) { int e = g_csr[rs + i]; sN = src[e]; eav = ea[e]; }
            else { sN = n; eav = loopv; }
#pragma unroll
            for (int h = 0; h < H; h++) {
                float v = g_asrc[sN * H + h] + s_adst[h] + s_chh[h] * eav;
                v = (v >= 0.f) ? v : 0.2f * v;
                s_alpha[tid * H + h] = expf(v - s_m[h]) / s_z[h];
            }
            s_sid[tid] = sN;
        }
        __syncthreads();
        int lim = min(CH, T - base);
        for (int j = 0; j < lim; j++)
            acc += s_alpha[j * H + hh] * hbuf[(size_t)s_sid[j] * OUT + tid];
        __syncthreads();
    }
    float v = acc + bias[tid];
    v = (v >= 0.f) ? v : 0.01f * v;
    out[(size_t)n * OUT + tid] = v + resid[(size_t)n * OUT + tid];
}

// ---------------- driver ----------------
extern "C" void kernel_launch(void* const* d_in, const int* in_sizes, int n_in,
                              void* d_out, int out_size) {
    const float* x     = (const float*)d_in[0];
    const int*   eidx  = (const int*)d_in[1];
    const float* ea    = (const float*)d_in[2];
    const float* fa_w  = (const float*)d_in[3];
    const float* fa_b  = (const float*)d_in[4];
    const float* W1    = (const float*)d_in[5];
    const float* We1   = (const float*)d_in[6];
    const float* as1   = (const float*)d_in[7];
    const float* ad1   = (const float*)d_in[8];
    const float* ae1   = (const float*)d_in[9];
    const float* b1    = (const float*)d_in[10];
    const float* W2    = (const float*)d_in[11];
    const float* We2   = (const float*)d_in[12];
    const float* as2   = (const float*)d_in[13];
    const float* ad2   = (const float*)d_in[14];
    const float* ae2   = (const float*)d_in[15];
    const float* b2    = (const float*)d_in[16];
    const float* W3    = (const float*)d_in[17];
    const float* We3   = (const float*)d_in[18];
    const float* as3   = (const float*)d_in[19];
    const float* ad3   = (const float*)d_in[20];
    const float* ae3   = (const float*)d_in[21];
    const float* b3    = (const float*)d_in[22];
    const float* r1_w  = (const float*)d_in[23];
    const float* r1_b  = (const float*)d_in[24];
    const float* r2_w  = (const float*)d_in[25];
    const float* r2_b  = (const float*)d_in[26];
    const float* ffn_w1 = (const float*)d_in[27];
    const float* ffn_b1 = (const float*)d_in[28];
    const float* ffn_w2 = (const float*)d_in[29];
    const float* ffn_b2 = (const float*)d_in[30];
    float* out = (float*)d_out;

    const int* src = eidx;
    const int* dst = eidx + NE;

    float *gx, *gh, *gz1, *gz2, *gres, *gzself, *gt64;
    cudaGetSymbolAddress((void**)&gx, g_x);
    cudaGetSymbolAddress((void**)&gh, g_h);
    cudaGetSymbolAddress((void**)&gz1, g_z1);
    cudaGetSymbolAddress((void**)&gz2, g_z2);
    cudaGetSymbolAddress((void**)&gres, g_res);
    cudaGetSymbolAddress((void**)&gzself, g_zself);
    cudaGetSymbolAddress((void**)&gt64, g_t64);

    const int TB = 256;
    const int nbN = (NN + TB - 1) / TB;
    const int nbE = (NE + TB - 1) / TB;

    // CSR build (feature-independent)
    zero_kernel<<<nbN, TB>>>();
    deg_kernel<<<nbE, TB>>>(dst, ea);
    loop_kernel<<<nbN, TB>>>();
    alloc_kernel<<<(NN + 1023) / 1024, 1024>>>();
    csr_kernel<<<nbE, TB>>>(dst);

    // feature gate: g_x = x * sigmoid(x @ fa_w + fa_b)
    launch_gemm(EP_GATE, x, fa_w, fa_b, gx, NN, 128, 128);

    // z_self = relu(g_x @ ffn_w1 + b) @ ffn_w2 + b
    launch_gemm(EP_RELU, gx, ffn_w1, ffn_b1, gt64, NN, 128, 64);
    launch_gemm(EP_NONE, gt64, ffn_w2, ffn_b2, gzself, NN, 64, 64);

    // --- layer 1 ---
    launch_gemm(EP_NONE, gx, r1_w, r1_b, gres, NN, 128, 256);
    launch_gemm(EP_NONE, gx, W1, nullptr, gh, NN, 128, 256);
    attn_kernel<4><<<(NN * 4 * 32 + TB - 1) / TB, TB>>>(gh, as1, ad1);
    ch_kernel<<<1, 4>>>(We1, ae1, 4, 64);
    agg_kernel<4, 64><<<NN, 256>>>(gh, src, ea, b1, gres, gz1);

    // --- layer 2 ---
    launch_gemm(EP_NONE, gz1, r2_w, r2_b, gres, NN, 256, 256);
    launch_gemm(EP_NONE, gz1, W2, nullptr, gh, NN, 256, 256);
    attn_kernel<4><<<(NN * 4 * 32 + TB - 1) / TB, TB>>>(gh, as2, ad2);
    ch_kernel<<<1, 4>>>(We2, ae2, 4, 64);
    agg_kernel<4, 64><<<NN, 256>>>(gh, src, ea, b2, gres, gz2);

    // --- layer 3 (H=1, C=64) ---
    launch_gemm(EP_NONE, gz2, W3, nullptr, gt64, NN, 256, 64);
    attn_kernel<1><<<(NN * 32 + TB - 1) / TB, TB>>>(gt64, as3, ad3);
    ch_kernel<<<1, 1>>>(We3, ae3, 1, 64);
    agg_kernel<1, 64><<<NN, 64>>>(gt64, src, ea, b3, gzself, out);
}

// round 3
// speedup vs baseline: 1.5258x; 1.3237x over previous
#include <cuda_runtime.h>
#include <cuda_bf16.h>
#include <math.h>
#include <stdint.h>

#define NN 50000
#define NE 800000

// ---------------- scratch (device globals; no allocs allowed) ----------------
__device__ float g_xh[NN * 128], g_xl[NN * 128];          // split of input x
__device__ float g_x[NN * 128];                            // gated x
__device__ float g_gxh[NN * 128], g_gxl[NN * 128];         // split of gated x
__device__ float g_hr[NN * 512];                           // [res | h] fused layer out
__device__ float g_z1[NN * 256], g_z1h[NN * 256], g_z1l[NN * 256];
__device__ float g_z2[NN * 256], g_z2h[NN * 256], g_z2l[NN * 256];
__device__ float g_t64[NN * 64], g_t64h[NN * 64], g_t64l[NN * 64];
__device__ float g_zself[NN * 64];
__device__ float g_h3[NN * 64];
__device__ float g_asrc[NN * 4];
__device__ float g_adst[NN * 4];
__device__ float g_loop[NN];
__device__ float g_easum[NN];
__device__ int   g_deg[NN];
__device__ int   g_rowstart[NN];
__device__ int   g_cursor[NN];
__device__ int   g_csr[NE];
__device__ float g_ch[4];
__device__ int   g_total;
// pre-split weights
__device__ float g_wfa_h[128 * 128], g_wfa_l[128 * 128];
__device__ float g_wb1_h[128 * 512], g_wb1_l[128 * 512];
__device__ float g_wb2_h[256 * 512], g_wb2_l[256 * 512];
__device__ float g_w3_h[256 * 64],  g_w3_l[256 * 64];
__device__ float g_wf1_h[128 * 64], g_wf1_l[128 * 64];
__device__ float g_wf2_h[64 * 64],  g_wf2_l[64 * 64];
__device__ float g_bb1[512], g_bb2[512];

__device__ __forceinline__ float sigf(float x) { return 1.f / (1.f + __expf(-x)); }

__device__ __forceinline__ void tf32_split(float x, float& hi, float& lo) {
    uint32_t uh;
    asm("cvt.rna.tf32.f32 %0, %1;" : "=r"(uh) : "f"(x));
    hi = __uint_as_float(uh);
    float r = x - hi;
    uint32_t ul;
    asm("cvt.rna.tf32.f32 %0, %1;" : "=r"(ul) : "f"(r));
    lo = __uint_as_float(ul);
}

__device__ __forceinline__ void mma_tf32(float* c, const uint32_t* a, const uint32_t* b) {
    asm volatile(
        "mma.sync.aligned.m16n8k8.row.col.f32.tf32.tf32.f32 "
        "{%0,%1,%2,%3}, {%4,%5,%6,%7}, {%8,%9}, {%0,%1,%2,%3};\n"
        : "+f"(c[0]), "+f"(c[1]), "+f"(c[2]), "+f"(c[3])
        : "r"(a[0]), "r"(a[1]), "r"(a[2]), "r"(a[3]), "r"(b[0]), "r"(b[1]));
}

// ---------------- pack / split kernels ----------------
__global__ void split_kernel(const float* __restrict__ s, float* __restrict__ dh,
                             float* __restrict__ dl, int n) {
    int i = blockIdx.x * blockDim.x + threadIdx.x;
    if (i < n) { float h, l; tf32_split(s[i], h, l); dh[i] = h; dl[i] = l; }
}
__global__ void fusepack_kernel(const float* __restrict__ A, const float* __restrict__ B,
                                float* __restrict__ dh, float* __restrict__ dl,
                                int rows, int half) {
    int i = blockIdx.x * blockDim.x + threadIdx.x;
    int tot = rows * 2 * half;
    if (i < tot) {
        int r = i / (2 * half), c = i % (2 * half);
        float v = (c < half) ? A[r * half + c] : B[r * half + c - half];
        float h, l; tf32_split(v, h, l); dh[i] = h; dl[i] = l;
    }
}
__global__ void biaspack_kernel(const float* __restrict__ r1b, const float* __restrict__ r2b) {
    int i = blockIdx.x * blockDim.x + threadIdx.x;
    if (i < 512) {
        g_bb1[i] = (i < 256) ? r1b[i] : 0.f;
        g_bb2[i] = (i < 256) ? r2b[i] : 0.f;
    }
}

// ---------------- TF32 GEMM, pre-split A/B, reg-prefetch pipeline -----------
#define EP_NONE 0
#define EP_GATE 1
#define EP_RELU 2

template <int EP, bool SPLITOUT>
__global__ __launch_bounds__(256) void gemm2(
    const float* __restrict__ Agh, const float* __restrict__ Agl,
    const float* __restrict__ Bgh, const float* __restrict__ Bgl,
    const float* __restrict__ bias, const float* __restrict__ gateA,
    float* __restrict__ C, float* __restrict__ Ch, float* __restrict__ Cl,
    int M, int K, int N) {
    __shared__ float Ash[128][20], Asl[128][20];
    __shared__ float Bsh[64][20],  Bsl[64][20];
    const int bm = blockIdx.y * 128, bn = blockIdx.x * 64;
    const int tid = threadIdx.x, lane = tid & 31, wid = tid >> 5;
    const int wm = wid >> 1, wn = wid & 1;
    const int lg = lane >> 2, lt = lane & 3;
    const int ar0 = tid >> 2, as0 = (tid & 3) * 4;          // A-load coords
    const int bkk = tid >> 4, bn4 = (tid & 15) * 4;          // B-load coords

    float acc[2][4][4];
#pragma unroll
    for (int mt = 0; mt < 2; mt++)
#pragma unroll
        for (int nt = 0; nt < 4; nt++)
#pragma unroll
            for (int j = 0; j < 4; j++) acc[mt][nt][j] = 0.f;

    float4 rah[2], ral[2], rbh, rbl;
    const float4 z4 = make_float4(0.f, 0.f, 0.f, 0.f);

    // prologue load (k0 = 0)
#pragma unroll
    for (int t = 0; t < 2; t++) {
        int r = ar0 + t * 64;
        if (bm + r < M) {
            rah[t] = *(const float4*)&Agh[(size_t)(bm + r) * K + as0];
            ral[t] = *(const float4*)&Agl[(size_t)(bm + r) * K + as0];
        } else { rah[t] = z4; ral[t] = z4; }
    }
    rbh = *(const float4*)&Bgh[(size_t)bkk * N + bn + bn4];
    rbl = *(const float4*)&Bgl[(size_t)bkk * N + bn + bn4];

    for (int k0 = 0; k0 < K; k0 += 16) {
        // stage regs -> smem
#pragma unroll
        for (int t = 0; t < 2; t++) {
            int r = ar0 + t * 64;
            Ash[r][as0 + 0] = rah[t].x; Ash[r][as0 + 1] = rah[t].y;
            Ash[r][as0 + 2] = rah[t].z; Ash[r][as0 + 3] = rah[t].w;
            Asl[r][as0 + 0] = ral[t].x; Asl[r][as0 + 1] = ral[t].y;
            Asl[r][as0 + 2] = ral[t].z; Asl[r][as0 + 3] = ral[t].w;
        }
        Bsh[bn4 + 0][bkk] = rbh.x; Bsh[bn4 + 1][bkk] = rbh.y;
        Bsh[bn4 + 2][bkk] = rbh.z; Bsh[bn4 + 3][bkk] = rbh.w;
        Bsl[bn4 + 0][bkk] = rbl.x; Bsl[bn4 + 1][bkk] = rbl.y;
        Bsl[bn4 + 2][bkk] = rbl.z; Bsl[bn4 + 3][bkk] = rbl.w;
        __syncthreads();
        // prefetch next tile
        if (k0 + 16 < K) {
            int kn = k0 + 16;
#pragma unroll
            for (int t = 0; t < 2; t++) {
                int r = ar0 + t * 64;
                if (bm + r < M) {
                    rah[t] = *(const float4*)&Agh[(size_t)(bm + r) * K + kn + as0];
                    ral[t] = *(const float4*)&Agl[(size_t)(bm + r) * K + kn + as0];
                } else { rah[t] = z4; ral[t] = z4; }
            }
            rbh = *(const float4*)&Bgh[(size_t)(kn + bkk) * N + bn + bn4];
            rbl = *(const float4*)&Bgl[(size_t)(kn + bkk) * N + bn + bn4];
        }
        // compute
#pragma unroll
        for (int ks = 0; ks < 16; ks += 8) {
            const int kc = ks + lt;
            uint32_t ah[2][4], al[2][4], bh[4][2], bl[4][2];
#pragma unroll
            for (int mt = 0; mt < 2; mt++) {
                int r = wm * 32 + mt * 16 + lg;
                ah[mt][0] = __float_as_uint(Ash[r][kc]);
                ah[mt][1] = __float_as_uint(Ash[r + 8][kc]);
                ah[mt][2] = __float_as_uint(Ash[r][kc + 4]);
                ah[mt][3] = __float_as_uint(Ash[r + 8][kc + 4]);
                al[mt][0] = __float_as_uint(Asl[r][kc]);
                al[mt][1] = __float_as_uint(Asl[r + 8][kc]);
                al[mt][2] = __float_as_uint(Asl[r][kc + 4]);
                al[mt][3] = __float_as_uint(Asl[r + 8][kc + 4]);
            }
#pragma unroll
            for (int nt = 0; nt < 4; nt++) {
                int c = wn * 32 + nt * 8 + lg;
                bh[nt][0] = __float_as_uint(Bsh[c][kc]);
                bh[nt][1] = __float_as_uint(Bsh[c][kc + 4]);
                bl[nt][0] = __float_as_uint(Bsl[c][kc]);
                bl[nt][1] = __float_as_uint(Bsl[c][kc + 4]);
            }
#pragma unroll
            for (int mt = 0; mt < 2; mt++)
#pragma unroll
                for (int nt = 0; nt < 4; nt++) {
                    mma_tf32(acc[mt][nt], ah[mt], bh[nt]);
                    mma_tf32(acc[mt][nt], al[mt], bh[nt]);
                    mma_tf32(acc[mt][nt], ah[mt], bl[nt]);
                }
        }
        __syncthreads();
    }
    // epilogue
#pragma unroll
    for (int mt = 0; mt < 2; mt++) {
        int r0 = bm + wm * 32 + mt * 16 + lg;
#pragma unroll
        for (int nt = 0; nt < 4; nt++) {
            int c0 = bn + wn * 32 + nt * 8 + lt * 2;
#pragma unroll
            for (int j = 0; j < 4; j++) {
                int row = r0 + (j >> 1) * 8;
                int col = c0 + (j & 1);
                if (row >= M) continue;
                float v = acc[mt][nt][j] + (bias ? bias[col] : 0.f);
                if (EP == EP_GATE) v = gateA[(size_t)row * K + col] * sigf(v);
                else if (EP == EP_RELU) v = fmaxf(v, 0.f);
                size_t idx = (size_t)row * N + col;
                C[idx] = v;
                if (SPLITOUT) {
                    float h, l; tf32_split(v, h, l);
                    Ch[idx] = h; Cl[idx] = l;
                }
            }
        }
    }
}

static void launch_gemm(int ep, bool split,
                        const float* Ah, const float* Al,
                        const float* Bh, const float* Bl,
                        const float* bias, const float* gateA,
                        float* C, float* Ch, float* Cl, int M, int K, int N) {
    dim3 grid(N / 64, (M + 127) / 128), blk(256);
    if (ep == EP_GATE) gemm2<EP_GATE, true><<<grid, blk>>>(Ah, Al, Bh, Bl, bias, gateA, C, Ch, Cl, M, K, N);
    else if (ep == EP_RELU) gemm2<EP_RELU, true><<<grid, blk>>>(Ah, Al, Bh, Bl, bias, gateA, C, Ch, Cl, M, K, N);
    else if (split) gemm2<EP_NONE, true><<<grid, blk>>>(Ah, Al, Bh, Bl, bias, gateA, C, Ch, Cl, M, K, N);
    else gemm2<EP_NONE, false><<<grid, blk>>>(Ah, Al, Bh, Bl, bias, gateA, C, Ch, Cl, M, K, N);
}

// ---------------- CSR build ----------------
__global__ void zero_kernel() {
    int i = blockIdx.x * blockDim.x + threadIdx.x;
    if (i < NN) { g_deg[i] = 0; g_cursor[i] = 0; g_easum[i] = 0.f; }
    if (i == 0) g_total = 0;
}
__global__ void deg_kernel(const int* __restrict__ dst, const float* __restrict__ ea) {
    int e = blockIdx.x * blockDim.x + threadIdx.x;
    if (e < NE) {
        int d = dst[e];
        atomicAdd(&g_deg[d], 1);
        atomicAdd(&g_easum[d], ea[e]);
    }
}
__global__ void loop_kernel() {
    int n = blockIdx.x * blockDim.x + threadIdx.x;
    if (n < NN) g_loop[n] = g_easum[n] / fmaxf((float)g_deg[n], 1.f);
}
__global__ void alloc_kernel() {
    __shared__ int s[1024];
    __shared__ int base;
    int tid = threadIdx.x;
    int i = blockIdx.x * 1024 + tid;
    int v = (i < NN) ? g_deg[i] : 0;
    s[tid] = v;
    __syncthreads();
    for (int off = 1; off < 1024; off <<= 1) {
        int t = (tid >= off) ? s[tid - off] : 0;
        __syncthreads();
        s[tid] += t;
        __syncthreads();
    }
    int incl = s[tid];
    if (tid == 1023) base = atomicAdd(&g_total, s[1023]);
    __syncthreads();
    if (i < NN) g_rowstart[i] = base + incl - v;
}
__global__ void csr_kernel(const int* __restrict__ dst) {
    int e = blockIdx.x * blockDim.x + threadIdx.x;
    if (e < NE) {
        int d = dst[e];
        int pos = atomicAdd(&g_cursor[d], 1);
        g_csr[g_rowstart[d] + pos] = e;
    }
}

// ---------------- attention coefficients ----------------
template <int H>
__global__ void attn_kernel(const float* __restrict__ hbuf, int stride,
                            const float* __restrict__ a_s, const float* __restrict__ a_d) {
    int w = (blockIdx.x * blockDim.x + threadIdx.x) >> 5;
    int lane = threadIdx.x & 31;
    if (w >= NN * H) return;
    int n = w / H, hh = w % H;
    const float* hr = hbuf + (size_t)n * stride + hh * 64;
    float as0 = a_s[hh * 64 + lane], as1 = a_s[hh * 64 + lane + 32];
    float ad0 = a_d[hh * 64 + lane], ad1 = a_d[hh * 64 + lane + 32];
    float h0 = hr[lane], h1 = hr[lane + 32];
    float vs = h0 * as0 + h1 * as1;
    float vd = h0 * ad0 + h1 * ad1;
#pragma unroll
    for (int off = 16; off > 0; off >>= 1) {
        vs += __shfl_down_sync(0xffffffffu, vs, off);
        vd += __shfl_down_sync(0xffffffffu, vd, off);
    }
    if (lane == 0) { g_asrc[w] = vs; g_adst[w] = vd; }
}

__global__ void ch_kernel(const float* __restrict__ We, const float* __restrict__ ae, int H, int C) {
    int h = threadIdx.x;
    if (h < H) {
        float s = 0.f;
        for (int c = 0; c < C; c++) s += We[h * C + c] * ae[h * C + c];
        g_ch[h] = s;
    }
}

// ---------------- per-node softmax aggregation (warp-0 online softmax) -------
template <int H, int C, bool SPLIT>
__global__ void agg2(const float* __restrict__ hbuf, int hstride,
                     const int* __restrict__ src, const float* __restrict__ ea,
                     const float* __restrict__ bias,
                     const float* __restrict__ resid, int rstride,
                     float* __restrict__ out, float* __restrict__ outh,
                     float* __restrict__ outl) {
    constexpr int OUT = H * C;
    constexpr int CH = 64;
    __shared__ float s_m[H], s_z[H], s_adst[H], s_chh[H];
    __shared__ float s_alpha[CH * H];
    __shared__ int s_sid[CH];

    const int n = blockIdx.x;
    const int tid = threadIdx.x;
    const int deg = g_deg[n];
    const int rs = g_rowstart[n];
    const int T = deg + 1;
    const float loopv = g_loop[n];

    if (tid < H) { s_adst[tid] = g_adst[n * H + tid]; s_chh[tid] = g_ch[tid]; }

    if (tid < 32) {
        float m[H], zz[H], adst[H], chh[H];
#pragma unroll
        for (int h = 0; h < H; h++) {
            adst[h] = g_adst[n * H + h]; chh[h] = g_ch[h];
            m[h] = -1e30f; zz[h] = 0.f;
        }
        for (int i = tid; i < T; i += 32) {
            int sN; float eav;
            if (i < deg) { int e = g_csr[rs + i]; sN = src[e]; eav = ea[e]; }
            else { sN = n; eav = loopv; }
#pragma unroll
            for (int h = 0; h < H; h++) {
                float v = g_asrc[sN * H + h] + adst[h] + chh[h] * eav;
                v = (v >= 0.f) ? v : 0.2f * v;
                float nm = fmaxf(m[h], v);
                zz[h] = zz[h] * __expf(m[h] - nm) + __expf(v - nm);
                m[h] = nm;
            }
        }
#pragma unroll
        for (int off = 16; off > 0; off >>= 1) {
#pragma unroll
            for (int h = 0; h < H; h++) {
                float om = __shfl_xor_sync(0xffffffffu, m[h], off);
                float oz = __shfl_xor_sync(0xffffffffu, zz[h], off);
                float nm = fmaxf(m[h], om);
                zz[h] = zz[h] * __expf(m[h] - nm) + oz * __expf(om - nm);
                m[h] = nm;
            }
        }
        if (tid == 0) {
#pragma unroll
            for (int h = 0; h < H; h++) { s_m[h] = m[h]; s_z[h] = zz[h]; }
        }
    }
    __syncthreads();

    // gather pass
    const int hh = tid / C;
    float acc = 0.f;
    for (int base = 0; base < T; base += CH) {
        int i = base + tid;
        if (tid < CH && i < T) {
            int sN; float eav;
            if (i < deg) { int e = g_csr[rs + i]; sN = src[e]; eav = ea[e]; }
            else { sN = n; eav = loopv; }
#pragma unroll
            for (int h = 0; h < H; h++) {
                float v = g_asrc[sN * H + h] + s_adst[h] + s_chh[h] * eav;
                v = (v >= 0.f) ? v : 0.2f * v;
                s_alpha[tid * H + h] = __expf(v - s_m[h]) / s_z[h];
            }
            s_sid[tid] = sN;
        }
        __syncthreads();
        int lim = min(CH, T - base);
        for (int j = 0; j < lim; j++)
            acc += s_alpha[j * H + hh] * hbuf[(size_t)s_sid[j] * hstride + tid];
        __syncthreads();
    }
    float v = acc + bias[tid];
    v = (v >= 0.f) ? v : 0.01f * v;
    v += resid[(size_t)n * rstride + tid];
    size_t idx = (size_t)n * OUT + tid;
    out[idx] = v;
    if (SPLIT) {
        float h, l; tf32_split(v, h, l);
        outh[idx] = h; outl[idx] = l;
    }
}

// ---------------- driver ----------------
extern "C" void kernel_launch(void* const* d_in, const int* in_sizes, int n_in,
                              void* d_out, int out_size) {
    const float* x     = (const float*)d_in[0];
    const int*   eidx  = (const int*)d_in[1];
    const float* ea    = (const float*)d_in[2];
    const float* fa_w  = (const float*)d_in[3];
    const float* fa_b  = (const float*)d_in[4];
    const float* W1    = (const float*)d_in[5];
    const float* We1   = (const float*)d_in[6];
    const float* as1   = (const float*)d_in[7];
    const float* ad1   = (const float*)d_in[8];
    const float* ae1   = (const float*)d_in[9];
    const float* b1    = (const float*)d_in[10];
    const float* W2    = (const float*)d_in[11];
    const float* We2   = (const float*)d_in[12];
    const float* as2   = (const float*)d_in[13];
    const float* ad2   = (const float*)d_in[14];
    const float* ae2   = (const float*)d_in[15];
    const float* b2    = (const float*)d_in[16];
    const float* W3    = (const float*)d_in[17];
    const float* We3   = (const float*)d_in[18];
    const float* as3   = (const float*)d_in[19];
    const float* ad3   = (const float*)d_in[20];
    const float* ae3   = (const float*)d_in[21];
    const float* b3    = (const float*)d_in[22];
    const float* r1_w  = (const float*)d_in[23];
    const float* r1_b  = (const float*)d_in[24];
    const float* r2_w  = (const float*)d_in[25];
    const float* r2_b  = (const float*)d_in[26];
    const float* ffn_w1 = (const float*)d_in[27];
    const float* ffn_b1 = (const float*)d_in[28];
    const float* ffn_w2 = (const float*)d_in[29];
    const float* ffn_b2 = (const float*)d_in[30];
    float* out = (float*)d_out;

    const int* src = eidx;
    const int* dst = eidx + NE;

    float *xh, *xl, *gx, *gxh, *gxl, *hr, *z1, *z1h, *z1l, *z2, *z2h, *z2l;
    float *t64, *t64h, *t64l, *zself, *h3;
    float *wfah, *wfal, *wb1h, *wb1l, *wb2h, *wb2l, *w3h, *w3l, *wf1h, *wf1l, *wf2h, *wf2l;
    cudaGetSymbolAddress((void**)&xh, g_xh);   cudaGetSymbolAddress((void**)&xl, g_xl);
    cudaGetSymbolAddress((void**)&gx, g_x);
    cudaGetSymbolAddress((void**)&gxh, g_gxh); cudaGetSymbolAddress((void**)&gxl, g_gxl);
    cudaGetSymbolAddress((void**)&hr, g_hr);
    cudaGetSymbolAddress((void**)&z1, g_z1);   cudaGetSymbolAddress((void**)&z1h, g_z1h);
    cudaGetSymbolAddress((void**)&z1l, g_z1l);
    cudaGetSymbolAddress((void**)&z2, g_z2);   cudaGetSymbolAddress((void**)&z2h, g_z2h);
    cudaGetSymbolAddress((void**)&z2l, g_z2l);
    cudaGetSymbolAddress((void**)&t64, g_t64); cudaGetSymbolAddress((void**)&t64h, g_t64h);
    cudaGetSymbolAddress((void**)&t64l, g_t64l);
    cudaGetSymbolAddress((void**)&zself, g_zself);
    cudaGetSymbolAddress((void**)&h3, g_h3);
    cudaGetSymbolAddress((void**)&wfah, g_wfa_h); cudaGetSymbolAddress((void**)&wfal, g_wfa_l);
    cudaGetSymbolAddress((void**)&wb1h, g_wb1_h); cudaGetSymbolAddress((void**)&wb1l, g_wb1_l);
    cudaGetSymbolAddress((void**)&wb2h, g_wb2_h); cudaGetSymbolAddress((void**)&wb2l, g_wb2_l);
    cudaGetSymbolAddress((void**)&w3h, g_w3_h);   cudaGetSymbolAddress((void**)&w3l, g_w3_l);
    cudaGetSymbolAddress((void**)&wf1h, g_wf1_h); cudaGetSymbolAddress((void**)&wf1l, g_wf1_l);
    cudaGetSymbolAddress((void**)&wf2h, g_wf2_h); cudaGetSymbolAddress((void**)&wf2l, g_wf2_l);
    float *bb1, *bb2;
    cudaGetSymbolAddress((void**)&bb1, g_bb1);
    cudaGetSymbolAddress((void**)&bb2, g_bb2);

    const int TB = 256;
    const int nbN = (NN + TB - 1) / TB;
    const int nbE = (NE + TB - 1) / TB;

    // CSR build
    zero_kernel<<<nbN, TB>>>();
    deg_kernel<<<nbE, TB>>>(dst, ea);
    loop_kernel<<<nbN, TB>>>();
    alloc_kernel<<<(NN + 1023) / 1024, 1024>>>();
    csr_kernel<<<nbE, TB>>>(dst);

    // weight pre-splits (tiny)
    split_kernel<<<(128 * 128 + 255) / 256, 256>>>(fa_w, wfah, wfal, 128 * 128);
    fusepack_kernel<<<(128 * 512 + 255) / 256, 256>>>(r1_w, W1, wb1h, wb1l, 128, 256);
    fusepack_kernel<<<(256 * 512 + 255) / 256, 256>>>(r2_w, W2, wb2h, wb2l, 256, 256);
    split_kernel<<<(256 * 64 + 255) / 256, 256>>>(W3, w3h, w3l, 256 * 64);
    split_kernel<<<(128 * 64 + 255) / 256, 256>>>(ffn_w1, wf1h, wf1l, 128 * 64);
    split_kernel<<<(64 * 64 + 255) / 256, 256>>>(ffn_w2, wf2h, wf2l, 64 * 64);
    biaspack_kernel<<<2, 256>>>(r1_b, r2_b);

    // split input x
    split_kernel<<<(NN * 128 + 255) / 256, 256>>>(x, xh, xl, NN * 128);

    // gate: gx = x * sigmoid(x @ fa_w + fa_b); writes gx + splits
    launch_gemm(EP_GATE, true, xh, xl, wfah, wfal, fa_b, x, gx, gxh, gxl, NN, 128, 128);

    // ffn: zself = relu(gx @ ffn_w1 + b) @ ffn_w2 + b
    launch_gemm(EP_RELU, true, gxh, gxl, wf1h, wf1l, ffn_b1, nullptr, t64, t64h, t64l, NN, 128, 64);
    launch_gemm(EP_NONE, false, t64h, t64l, wf2h, wf2l, ffn_b2, nullptr, zself, nullptr, nullptr, NN, 64, 64);

    // --- layer 1: fused [res | h] = gx @ [r1_w | W1] ---
    launch_gemm(EP_NONE, false, gxh, gxl, wb1h, wb1l, bb1, nullptr, hr, nullptr, nullptr, NN, 128, 512);
    attn_kernel<4><<<(NN * 4 * 32 + TB - 1) / TB, TB>>>(hr + 256, 512, as1, ad1);
    ch_kernel<<<1, 4>>>(We1, ae1, 4, 64);
    agg2<4, 64, true><<<NN, 256>>>(hr + 256, 512, src, ea, b1, hr, 512, z1, z1h, z1l);

    // --- layer 2 ---
    launch_gemm(EP_NONE, false, z1h, z1l, wb2h, wb2l, bb2, nullptr, hr, nullptr, nullptr, NN, 256, 512);
    attn_kernel<4><<<(NN * 4 * 32 + TB - 1) / TB, TB>>>(hr + 256, 512, as2, ad2);
    ch_kernel<<<1, 4>>>(We2, ae2, 4, 64);
    agg2<4, 64, true><<<NN, 256>>>(hr + 256, 512, src, ea, b2, hr, 512, z2, z2h, z2l);

    // --- layer 3 (H=1, C=64) ---
    launch_gemm(EP_NONE, false, z2h, z2l, w3h, w3l, nullptr, nullptr, h3, nullptr, nullptr, NN, 256, 64);
    attn_kernel<1><<<(NN * 32 + TB - 1) / TB, TB>>>(h3, 64, as3, ad3);
    ch_kernel<<<1, 1>>>(We3, ae3, 1, 64);
    agg2<1, 64, false><<<NN, 64>>>(h3, 64, src, ea, b3, zself, 64, out, nullptr, nullptr);
}